// round 2
// baseline (speedup 1.0000x reference)
#include <cuda_runtime.h>
#include <cstdint>

// Problem constants (fixed shapes for FrameGenerator_50517405335887)
#define S_NUM 16      // samples
#define F_NUM 16      // frames
#define FS 128        // frame size
#define PLANE (FS*FS) // 16384

// Flag: 1 if event_indices is int64, 0 if int32. Set by detect_kernel.
__device__ int g_idx64;

// Detect index dtype. For int64 (values < 2^31, non-negative), every odd
// 32-bit word of the x-row (which spans words [2N, 4N) under int64 layout)
// is zero. For int32, those same words are y[1], y[3], ... — random in
// [0,128), all-zero with probability 128^-32.
__global__ void detect_dtype_kernel(const int32_t* __restrict__ idx, long long N)
{
    if (threadIdx.x == 0 && blockIdx.x == 0) {
        int allz = 1;
        #pragma unroll
        for (int k = 0; k < 32; k++) {
            if (idx[2 * N + 2 * k + 1] != 0) { allz = 0; break; }
        }
        g_idx64 = allz;
    }
}

// Scatter-add events into frames.
// out layout: [F, S, 2, Y, X] fp32.
//   out[((((f*S + s)*2 + p)*FS + y)*FS + x)] ; p=0 neg, p=1 pos
// Each thread handles one event n for all 16 samples.
// W (events per frame) = N / F_NUM = 65536, divisible by blockDim -> frame id
// is uniform per block; compute it once from the block's first event.
__global__ __launch_bounds__(256)
void scatter_kernel(const float* __restrict__ vals,
                    const int32_t* __restrict__ idx32,
                    float* __restrict__ out,
                    int N, int W)
{
    const int n = blockIdx.x * blockDim.x + threadIdx.x;
    if (n >= N) return;

    int x, y;
    if (g_idx64) {
        const long long* idx64 = (const long long*)idx32;
        x = (int)idx64[(long long)N + n];
        y = (int)idx64[2LL * N + n];
    } else {
        x = idx32[N + n];
        y = idx32[2 * N + n];
    }

    const int f = (blockIdx.x * blockDim.x) / W;   // uniform across block

    // base pointer for (f, s=0, p=0, y, x)
    float* base = out + (size_t)f * (S_NUM * 2 * PLANE) + y * FS + x;

    #pragma unroll
    for (int s = 0; s < S_NUM; s++) {
        const float v = vals[(size_t)s * N + n];
        if (v > 0.0f) {
            atomicAdd(base + (size_t)(s * 2 + 1) * PLANE, v);    // pos plane
        } else if (v < 0.0f) {
            atomicAdd(base + (size_t)(s * 2) * PLANE, -v);       // neg plane
        }
    }
}

extern "C" void kernel_launch(void* const* d_in, const int* in_sizes, int n_in,
                              void* d_out, int out_size)
{
    const float*   vals  = (const float*)d_in[0];
    const int32_t* idx   = (const int32_t*)d_in[1];
    float*         out   = (float*)d_out;

    const int N = in_sizes[0] / S_NUM;     // events (1048576)
    const int W = N / F_NUM;               // events per frame (65536)

    // Output is poisoned; zero it (32 MB).
    cudaMemsetAsync(d_out, 0, (size_t)out_size * sizeof(float), 0);

    detect_dtype_kernel<<<1, 32>>>(idx, (long long)N);

    const int threads = 256;
    const int blocks = (N + threads - 1) / threads;
    scatter_kernel<<<blocks, threads>>>(vals, idx, out, N, W);
}

// round 5
// speedup vs baseline: 1.3869x; 1.3869x over previous
#include <cuda_runtime.h>
#include <cstdint>

#define S_NUM 16      // samples
#define F_NUM 16      // frames
#define FS 128        // frame size
#define PLANE (FS*FS) // 16384

// Scratch in event-friendly layout [F, Y, X, S, 2] : 16*16384*32 floats = 32 MB.
__device__ float g_scratch[(size_t)F_NUM * PLANE * S_NUM * 2];

// Flag: 1 if event_indices is int64, 0 if int32.
__device__ int g_idx64;

// For int64 (values in [0,2^31), LE), every odd 32-bit word of the x-row is 0.
// For int32 those words are random y-values in [0,128). P(misdetect) = 128^-32.
__global__ void detect_dtype_kernel(const int32_t* __restrict__ idx, long long N)
{
    if (threadIdx.x == 0 && blockIdx.x == 0) {
        int allz = 1;
        #pragma unroll
        for (int k = 0; k < 32; k++) {
            if (idx[2 * N + 2 * k + 1] != 0) { allz = 0; break; }
        }
        g_idx64 = allz;
    }
}

// Scatter: one thread per event. All 16 samples' (neg,pos) pairs for this
// event land in 32 consecutive floats of scratch -> 8 float4 vector atomics.
__global__ __launch_bounds__(256)
void scatter_kernel(const float* __restrict__ vals,
                    const int32_t* __restrict__ idx32,
                    int N, int W)
{
    const int n = blockIdx.x * blockDim.x + threadIdx.x;
    if (n >= N) return;

    int x, y;
    if (g_idx64) {
        const long long* idx64 = (const long long*)idx32;
        x = (int)idx64[(long long)N + n];
        y = (int)idx64[2LL * N + n];
    } else {
        x = idx32[N + n];
        y = idx32[2 * N + n];
    }

    const int f = (blockIdx.x * blockDim.x) / W;   // uniform per block (W%256==0)

    // base for (f, y, x, s=0, p=0); 128B-aligned.
    float4* base = (float4*)(g_scratch +
        ((size_t)f * PLANE + (size_t)y * FS + x) * (S_NUM * 2));

    #pragma unroll
    for (int k = 0; k < 8; k++) {
        const float v0 = vals[(size_t)(2 * k)     * N + n];
        const float v1 = vals[(size_t)(2 * k + 1) * N + n];
        float4 u;
        u.x = fmaxf(-v0, 0.0f);   // neg, sample 2k
        u.y = fmaxf( v0, 0.0f);   // pos, sample 2k
        u.z = fmaxf(-v1, 0.0f);   // neg, sample 2k+1
        u.w = fmaxf( v1, 0.0f);   // pos, sample 2k+1
        atomicAdd(base + k, u);   // RED.E.ADD.F32x4 (sm_90+)
    }
}

// Transpose scratch [F, pos, sp] (pos = y*FS+x flat, sp = s*2+p)
//            -> out [F, s, p, pos].  Tile: 64 positions x 32 sp = 8 KB smem.
__global__ __launch_bounds__(256)
void transpose_kernel(float* __restrict__ out)
{
    __shared__ float tile[64][33];   // pad to kill bank conflicts

    const int f  = blockIdx.x >> 8;          // 256 tiles per frame
    const int p0 = (blockIdx.x & 255) * 64;  // first flat position of tile
    const int t  = threadIdx.x;

    // Load 64*32 floats coalesced as float4 (512 float4s, 2 per thread).
    const float4* src = (const float4*)(g_scratch +
        ((size_t)f * PLANE + p0) * (S_NUM * 2));
    #pragma unroll
    for (int r = 0; r < 2; r++) {
        const int j = r * 256 + t;           // float4 index 0..511
        const float4 v = src[j];
        const int fi  = j * 4;               // flat float index
        const int pos = fi >> 5;             // /32
        const int sp  = fi & 31;
        tile[pos][sp]     = v.x;
        tile[pos][sp + 1] = v.y;
        tile[pos][sp + 2] = v.z;
        tile[pos][sp + 3] = v.w;
    }
    __syncthreads();

    // Write: for each sp, 64 consecutive positions -> coalesced 256B rows.
    #pragma unroll
    for (int r = 0; r < 8; r++) {
        const int e   = r * 256 + t;         // 0..2047
        const int sp  = e >> 6;              // /64
        const int pos = e & 63;
        // out[((f*S + s)*2 + p)*PLANE + p0 + pos], sp = s*2+p
        out[((size_t)f * (S_NUM * 2) + sp) * PLANE + p0 + pos] = tile[pos][sp];
    }
}

extern "C" void kernel_launch(void* const* d_in, const int* in_sizes, int n_in,
                              void* d_out, int out_size)
{
    const float*   vals = (const float*)d_in[0];
    const int32_t* idx  = (const int32_t*)d_in[1];
    float*         out  = (float*)d_out;

    const int N = in_sizes[0] / S_NUM;     // 1048576 events
    const int W = N / F_NUM;               // 65536 events per frame

    void* scratch_ptr = nullptr;
    cudaGetSymbolAddress(&scratch_ptr, g_scratch);
    cudaMemsetAsync(scratch_ptr, 0,
                    (size_t)F_NUM * PLANE * S_NUM * 2 * sizeof(float), 0);

    detect_dtype_kernel<<<1, 32>>>(idx, (long long)N);

    const int threads = 256;
    scatter_kernel<<<(N + threads - 1) / threads, threads>>>(vals, idx, N, W);

    // Transpose writes every output element -> no out memset needed.
    transpose_kernel<<<F_NUM * (PLANE / 64), 256>>>(out);
}